// round 1
// baseline (speedup 1.0000x reference)
#include <cuda_runtime.h>
#include <math.h>

#define HIDDEN 1024
#define NH 16
#define NKV 4
#define HD 64
#define SEQL 2048
#define BSZ 2
#define KVD (NKV*HD)            /* 256  */
#define QKVN (HIDDEN + 2*KVD)   /* 1536 */
#define MTOT (BSZ*SEQL)         /* 4096 */
#define WIN 1534                /* allowed: kj - qi <= 1534 */
#define ATTN_SMEM ((64*64 + 64*68 + 64*64 + 64*64) * 4)  /* 66560 B */

// Scratch (static device arrays: allocation-free contract)
__device__ float  g_qkv[(size_t)MTOT * QKVN];
__device__ float  g_attn[(size_t)MTOT * HIDDEN];
__device__ float2 g_sc[SEQL * 32];

// ---------------------------------------------------------------------------
// sin/cos table: high-precision angles (double), only 65536 threads
// ---------------------------------------------------------------------------
__global__ void sincos_kernel() {
    int idx = blockIdx.x * blockDim.x + threadIdx.x;
    if (idx >= SEQL * 32) return;
    int s = idx >> 5, j = idx & 31;
    // inv_freq = 10000^(-j/32) = exp(-j * ln(10000)/32)
    double invf = exp(-(double)j * 0.28782313662425572);
    double ang  = (double)s * invf;
    g_sc[idx] = make_float2((float)sin(ang), (float)cos(ang));
}

// ---------------------------------------------------------------------------
// RoPE in-place on q (cols 0..1023) and k (cols 1024..1279) of g_qkv
// ---------------------------------------------------------------------------
__global__ void rope_kernel(float* __restrict__ qkv) {
    int idx = blockIdx.x * blockDim.x + threadIdx.x;
    if (idx >= MTOT * (NH + NKV) * (HD / 2)) return;
    int j = idx & 31;
    int t = idx >> 5;
    int h = t % (NH + NKV);
    int m = t / (NH + NKV);
    int s = m & (SEQL - 1);
    float2 sc = g_sc[(s << 5) | j];      // x = sin, y = cos
    float* base = qkv + (size_t)m * QKVN + (h < NH ? h * HD : HIDDEN + (h - NH) * HD);
    float xr = base[j];
    float xp = base[j + 32];
    base[j]      = xr * sc.y - xp * sc.x;
    base[j + 32] = xr * sc.x + xp * sc.y;
}

// ---------------------------------------------------------------------------
// Tiled fp32 GEMM: C[m,n] = sum_k A[m,k] * B[n,k] (+ bias[n])
// BM=BN=128, BK=16, 256 threads, 8x8 per thread.
// B / bias pointers selected per N-tile (tile never straddles n1/n2).
// ---------------------------------------------------------------------------
__global__ __launch_bounds__(256) void sgemm_kernel(
    const float* __restrict__ A,
    const float* __restrict__ B0, const float* __restrict__ B1, const float* __restrict__ B2,
    const float* __restrict__ c0p, const float* __restrict__ c1p, const float* __restrict__ c2p,
    float* __restrict__ C, int M, int N, int K, int n1, int n2)
{
    __shared__ float As[16][128];
    __shared__ float Bs[16][128];
    const int bm = blockIdx.y * 128;
    const int bn = blockIdx.x * 128;
    const int tid = threadIdx.x;

    const float* Bsel; const float* bias; int noff;
    if (bn < n1)      { Bsel = B0; bias = c0p; noff = bn; }
    else if (bn < n2) { Bsel = B1; bias = c1p; noff = bn - n1; }
    else              { Bsel = B2; bias = c2p; noff = bn - n2; }

    const int trow = (tid >> 4) * 8;
    const int tcol = (tid & 15) * 8;

    float acc[8][8];
    #pragma unroll
    for (int i = 0; i < 8; i++)
        #pragma unroll
        for (int j = 0; j < 8; j++) acc[i][j] = 0.f;

    for (int k0 = 0; k0 < K; k0 += 16) {
        #pragma unroll
        for (int l = 0; l < 2; l++) {
            int idx = tid + l * 256;
            int row = idx >> 2;
            int c4  = (idx & 3) * 4;
            float4 av = *(const float4*)(A + (size_t)(bm + row) * K + k0 + c4);
            As[c4 + 0][row] = av.x; As[c4 + 1][row] = av.y;
            As[c4 + 2][row] = av.z; As[c4 + 3][row] = av.w;
            float4 bv = *(const float4*)(Bsel + (size_t)(noff + row) * K + k0 + c4);
            Bs[c4 + 0][row] = bv.x; Bs[c4 + 1][row] = bv.y;
            Bs[c4 + 2][row] = bv.z; Bs[c4 + 3][row] = bv.w;
        }
        __syncthreads();
        #pragma unroll
        for (int kk = 0; kk < 16; kk++) {
            float a[8], b[8];
            *(float4*)&a[0] = *(const float4*)&As[kk][trow];
            *(float4*)&a[4] = *(const float4*)&As[kk][trow + 4];
            *(float4*)&b[0] = *(const float4*)&Bs[kk][tcol];
            *(float4*)&b[4] = *(const float4*)&Bs[kk][tcol + 4];
            #pragma unroll
            for (int i = 0; i < 8; i++)
                #pragma unroll
                for (int j = 0; j < 8; j++) acc[i][j] += a[i] * b[j];
        }
        __syncthreads();
    }

    float bb[8];
    if (bias) {
        #pragma unroll
        for (int j = 0; j < 8; j++) bb[j] = bias[noff + tcol + j];
    } else {
        #pragma unroll
        for (int j = 0; j < 8; j++) bb[j] = 0.f;
    }
    #pragma unroll
    for (int i = 0; i < 8; i++) {
        float* crow = C + (size_t)(bm + trow + i) * N + bn + tcol;
        float4 v0 = make_float4(acc[i][0] + bb[0], acc[i][1] + bb[1],
                                acc[i][2] + bb[2], acc[i][3] + bb[3]);
        float4 v1 = make_float4(acc[i][4] + bb[4], acc[i][5] + bb[5],
                                acc[i][6] + bb[6], acc[i][7] + bb[7]);
        *(float4*)crow       = v0;
        *(float4*)(crow + 4) = v1;
    }
}

// ---------------------------------------------------------------------------
// Flash attention, fp32, Br=Bc=64, D=64, 256 threads (16x16, 4x4 each).
// Mask: -inf where kj - qi > WIN; plus attention_mask[b,kj] * -1e4.
// GQA: kv head = h/4. qkv layout per row: [q(1024) | k(256) | v(256)].
// ---------------------------------------------------------------------------
__global__ __launch_bounds__(256) void attn_kernel(
    const float* __restrict__ qkv, const float* __restrict__ amask,
    float* __restrict__ out)
{
    extern __shared__ float smf[];
    float* Qs = smf;                 // [64][64]
    float* Kt = smf + 64 * 64;       // [64][68]  (d-major, padded)
    float* Vs = Kt + 64 * 68;        // [64][64]  (key-major)
    float* Ps = Vs + 64 * 64;        // [64][64]

    const int qt0 = blockIdx.x * 64;
    const int b   = blockIdx.y >> 4;
    const int h   = blockIdx.y & 15;
    const int kvh = h >> 2;
    const int tid = threadIdx.x;
    const int tx  = tid & 15;
    const int ty  = tid >> 4;
    const int r0  = ty * 4;
    const int c0  = tx * 4;

    const float* qbase = qkv + (size_t)(b * SEQL + qt0) * QKVN + h * HD;
    #pragma unroll
    for (int l = 0; l < 4; l++) {
        int idx = tid + l * 256;
        int r   = idx >> 4;
        int c4  = (idx & 15) * 4;
        *(float4*)&Qs[r * 64 + c4] = *(const float4*)(qbase + (size_t)r * QKVN + c4);
    }

    float m_i[4], l_i[4], o[4][4];
    #pragma unroll
    for (int i = 0; i < 4; i++) {
        m_i[i] = -1e30f; l_i[i] = 0.f;
        #pragma unroll
        for (int j = 0; j < 4; j++) o[i][j] = 0.f;
    }

    const int ktmax = min(SEQL, qt0 + 63 + WIN + 1);
    for (int kt0 = 0; kt0 < ktmax; kt0 += 64) {
        const float* kbase = qkv + (size_t)(b * SEQL + kt0) * QKVN + HIDDEN + kvh * HD;
        #pragma unroll
        for (int l = 0; l < 4; l++) {
            int idx = tid + l * 256;
            int c   = idx >> 4;
            int d4  = (idx & 15) * 4;
            float4 kv4 = *(const float4*)(kbase + (size_t)c * QKVN + d4);
            Kt[(d4 + 0) * 68 + c] = kv4.x;
            Kt[(d4 + 1) * 68 + c] = kv4.y;
            Kt[(d4 + 2) * 68 + c] = kv4.z;
            Kt[(d4 + 3) * 68 + c] = kv4.w;
            *(float4*)&Vs[c * 64 + d4] = *(const float4*)(kbase + KVD + (size_t)c * QKVN + d4);
        }
        __syncthreads();

        // S = Q K^T (raw)
        float sacc[4][4];
        #pragma unroll
        for (int i = 0; i < 4; i++)
            #pragma unroll
            for (int j = 0; j < 4; j++) sacc[i][j] = 0.f;

        #pragma unroll
        for (int d4 = 0; d4 < 64; d4 += 4) {
            float qv[4][4];
            #pragma unroll
            for (int i = 0; i < 4; i++) {
                float4 t = *(const float4*)&Qs[(r0 + i) * 64 + d4];
                qv[i][0] = t.x; qv[i][1] = t.y; qv[i][2] = t.z; qv[i][3] = t.w;
            }
            #pragma unroll
            for (int dd = 0; dd < 4; dd++) {
                float4 kf = *(const float4*)&Kt[(d4 + dd) * 68 + c0];
                float kj[4]; kj[0] = kf.x; kj[1] = kf.y; kj[2] = kf.z; kj[3] = kf.w;
                #pragma unroll
                for (int i = 0; i < 4; i++)
                    #pragma unroll
                    for (int j = 0; j < 4; j++)
                        sacc[i][j] += qv[i][dd] * kj[j];
            }
        }

        // scale + masks
        float amv[4];
        #pragma unroll
        for (int j = 0; j < 4; j++)
            amv[j] = amask[(size_t)b * SEQL + kt0 + c0 + j] * -10000.0f;

        #pragma unroll
        for (int i = 0; i < 4; i++) {
            int qi = qt0 + r0 + i;
            #pragma unroll
            for (int j = 0; j < 4; j++) {
                int kj = kt0 + c0 + j;
                float v = sacc[i][j] * 0.125f + amv[j];
                sacc[i][j] = (kj - qi > WIN) ? -1e30f : v;
            }
        }

        // online softmax (reduce across 16 lanes of the row group)
        #pragma unroll
        for (int i = 0; i < 4; i++) {
            float mx = fmaxf(fmaxf(sacc[i][0], sacc[i][1]), fmaxf(sacc[i][2], sacc[i][3]));
            #pragma unroll
            for (int off = 8; off >= 1; off >>= 1)
                mx = fmaxf(mx, __shfl_xor_sync(0xffffffffu, mx, off, 16));
            float mn    = fmaxf(m_i[i], mx);
            float alpha = __expf(m_i[i] - mn);
            m_i[i] = mn;
            float p0 = __expf(sacc[i][0] - mn);
            float p1 = __expf(sacc[i][1] - mn);
            float p2 = __expf(sacc[i][2] - mn);
            float p3 = __expf(sacc[i][3] - mn);
            *(float4*)&Ps[(r0 + i) * 64 + c0] = make_float4(p0, p1, p2, p3);
            float ls = p0 + p1 + p2 + p3;
            #pragma unroll
            for (int off = 8; off >= 1; off >>= 1)
                ls += __shfl_xor_sync(0xffffffffu, ls, off, 16);
            l_i[i] = l_i[i] * alpha + ls;
            #pragma unroll
            for (int j = 0; j < 4; j++) o[i][j] *= alpha;
        }
        __syncthreads();

        // O += P V  (thread dims = c0..c0+3)
        #pragma unroll 8
        for (int c = 0; c < 64; c++) {
            float4 vv = *(const float4*)&Vs[c * 64 + c0];
            float vj[4]; vj[0] = vv.x; vj[1] = vv.y; vj[2] = vv.z; vj[3] = vv.w;
            #pragma unroll
            for (int i = 0; i < 4; i++) {
                float p = Ps[(r0 + i) * 64 + c];
                #pragma unroll
                for (int j = 0; j < 4; j++) o[i][j] += p * vj[j];
            }
        }
        __syncthreads();
    }

    float* obase = out + (size_t)(b * SEQL + qt0) * HIDDEN + h * HD;
    #pragma unroll
    for (int i = 0; i < 4; i++) {
        float inv = 1.0f / l_i[i];
        float4 ov = make_float4(o[i][0] * inv, o[i][1] * inv, o[i][2] * inv, o[i][3] * inv);
        *(float4*)(obase + (size_t)(r0 + i) * HIDDEN + c0) = ov;
    }
}

// ---------------------------------------------------------------------------
extern "C" void kernel_launch(void* const* d_in, const int* in_sizes, int n_in,
                              void* d_out, int out_size) {
    const float* hs = (const float*)d_in[0];
    const float* am = (const float*)d_in[1];
    const float* Wq = (const float*)d_in[2];
    const float* bq = (const float*)d_in[3];
    const float* Wk = (const float*)d_in[4];
    const float* bk = (const float*)d_in[5];
    const float* Wv = (const float*)d_in[6];
    const float* bv = (const float*)d_in[7];
    const float* Wo = (const float*)d_in[8];
    float* out = (float*)d_out;

    float* qkv  = nullptr;
    float* attn = nullptr;
    cudaGetSymbolAddress((void**)&qkv,  g_qkv);
    cudaGetSymbolAddress((void**)&attn, g_attn);

    // sin/cos table (cheap, recomputed every call: deterministic)
    sincos_kernel<<<(SEQL * 32 + 255) / 256, 256>>>();

    // fused QKV projection + bias -> g_qkv [4096 x 1536]
    sgemm_kernel<<<dim3(QKVN / 128, MTOT / 128), 256>>>(
        hs, Wq, Wk, Wv, bq, bk, bv, qkv,
        MTOT, QKVN, HIDDEN, HIDDEN, HIDDEN + KVD);

    // RoPE in-place on q and k
    rope_kernel<<<(MTOT * (NH + NKV) * (HD / 2) + 255) / 256, 256>>>(qkv);

    // flash attention -> g_attn [4096 x 1024]
    cudaFuncSetAttribute(attn_kernel, cudaFuncAttributeMaxDynamicSharedMemorySize, ATTN_SMEM);
    attn_kernel<<<dim3(SEQL / 64, BSZ * NH), 256, ATTN_SMEM>>>(qkv, am, attn);

    // output projection -> d_out
    sgemm_kernel<<<dim3(HIDDEN / 128, MTOT / 128), 256>>>(
        attn, Wo, Wo, Wo, nullptr, nullptr, nullptr, out,
        MTOT, HIDDEN, HIDDEN, 1 << 30, 1 << 30);
}

// round 2
// speedup vs baseline: 1.7886x; 1.7886x over previous
#include <cuda_runtime.h>
#include <cuda_bf16.h>
#include <math.h>

#define HIDDEN 1024
#define NH 16
#define NKV 4
#define HD 64
#define SEQL 2048
#define BSZ 2
#define KVD (NKV*HD)            /* 256  */
#define QKVN (HIDDEN + 2*KVD)   /* 1536 */
#define MTOT (BSZ*SEQL)         /* 4096 */
#define WIN 1534                /* allowed: kj - qi <= 1534 */

// Scratch (static device arrays: allocation-free contract)
__device__ float  g_qkv[(size_t)MTOT * QKVN];
__device__ float  g_attn[(size_t)MTOT * HIDDEN];
__device__ float2 g_sc[SEQL * 32];

// ---------------------------------------------------------------------------
// helpers
// ---------------------------------------------------------------------------
__device__ __forceinline__ void mma_bf16(float* c, const unsigned* a, const unsigned* b) {
    asm volatile(
        "mma.sync.aligned.m16n8k16.row.col.f32.bf16.bf16.f32 "
        "{%0,%1,%2,%3}, {%4,%5,%6,%7}, {%8,%9}, {%0,%1,%2,%3};"
        : "+f"(c[0]), "+f"(c[1]), "+f"(c[2]), "+f"(c[3])
        : "r"(a[0]), "r"(a[1]), "r"(a[2]), "r"(a[3]), "r"(b[0]), "r"(b[1]));
}

// split x,y into bf16 hi/lo pairs packed as (lo-half = x, hi-half = y)
__device__ __forceinline__ void split_pack2(float x, float y, unsigned& hi, unsigned& lo) {
    __nv_bfloat16 hx = __float2bfloat16(x);
    __nv_bfloat16 hy = __float2bfloat16(y);
    __nv_bfloat16 lx = __float2bfloat16(x - __bfloat162float(hx));
    __nv_bfloat16 ly = __float2bfloat16(y - __bfloat162float(hy));
    hi = ((unsigned)__bfloat16_as_ushort(hy) << 16) | (unsigned)__bfloat16_as_ushort(hx);
    lo = ((unsigned)__bfloat16_as_ushort(ly) << 16) | (unsigned)__bfloat16_as_ushort(lx);
}

__device__ __forceinline__ void split_store4(float4 v, __nv_bfloat16* hp, __nv_bfloat16* lp) {
    uint2 h, l;
    split_pack2(v.x, v.y, h.x, l.x);
    split_pack2(v.z, v.w, h.y, l.y);
    *(uint2*)hp = h;
    *(uint2*)lp = l;
}

// ---------------------------------------------------------------------------
// sin/cos table (double-precision angles)
// ---------------------------------------------------------------------------
__global__ void sincos_kernel() {
    int idx = blockIdx.x * blockDim.x + threadIdx.x;
    if (idx >= SEQL * 32) return;
    int s = idx >> 5, j = idx & 31;
    double invf = exp(-(double)j * 0.28782313662425572);
    double ang  = (double)s * invf;
    g_sc[idx] = make_float2((float)sin(ang), (float)cos(ang));
}

// ---------------------------------------------------------------------------
// RoPE in-place on q (cols 0..1023) and k (cols 1024..1279) of g_qkv
// ---------------------------------------------------------------------------
__global__ void rope_kernel(float* __restrict__ qkv) {
    int idx = blockIdx.x * blockDim.x + threadIdx.x;
    if (idx >= MTOT * (NH + NKV) * (HD / 2)) return;
    int j = idx & 31;
    int t = idx >> 5;
    int h = t % (NH + NKV);
    int m = t / (NH + NKV);
    int s = m & (SEQL - 1);
    float2 sc = g_sc[(s << 5) | j];
    float* base = qkv + (size_t)m * QKVN + (h < NH ? h * HD : HIDDEN + (h - NH) * HD);
    float xr = base[j];
    float xp = base[j + 32];
    base[j]      = xr * sc.y - xp * sc.x;
    base[j + 32] = xr * sc.x + xp * sc.y;
}

// ---------------------------------------------------------------------------
// bf16-split tensor-core GEMM: C[m,n] = sum_k A[m,k]*B[n,k] (+bias[n])
// BM=BN=128, BK=32, 256 thr = 8 warps (2x4), warp tile 64x32, m16n8k16 mma.
// 3-term split: Ah*Bh + Ah*Bl + Al*Bh  (near-fp32 accuracy).
// ---------------------------------------------------------------------------
#define BKP 40
__global__ __launch_bounds__(256) void hgemm_kernel(
    const float* __restrict__ A,
    const float* __restrict__ B0, const float* __restrict__ B1, const float* __restrict__ B2,
    const float* __restrict__ c0p, const float* __restrict__ c1p, const float* __restrict__ c2p,
    float* __restrict__ C, int M, int N, int K, int n1, int n2)
{
    __shared__ __align__(16) __nv_bfloat16 Ah[128][BKP], Al[128][BKP];
    __shared__ __align__(16) __nv_bfloat16 Bh[128][BKP], Bl[128][BKP];

    const int bm = blockIdx.y * 128;
    const int bn = blockIdx.x * 128;

    const float* Bsel; const float* bias; int noff;
    if (bn < n1)      { Bsel = B0; bias = c0p; noff = bn; }
    else if (bn < n2) { Bsel = B1; bias = c1p; noff = bn - n1; }
    else              { Bsel = B2; bias = c2p; noff = bn - n2; }

    const int tid  = threadIdx.x;
    const int wid  = tid >> 5;
    const int lane = tid & 31;
    const int g = lane >> 2, t = lane & 3;
    const int wm = (wid >> 2) * 64;
    const int wn = (wid & 3) * 32;

    float acc[4][4][4];
    #pragma unroll
    for (int i = 0; i < 4; i++)
        #pragma unroll
        for (int j = 0; j < 4; j++)
            #pragma unroll
            for (int c = 0; c < 4; c++) acc[i][j][c] = 0.f;

    for (int k0 = 0; k0 < K; k0 += 32) {
        #pragma unroll
        for (int l = 0; l < 4; l++) {
            int idx = tid + l * 256;
            int row = idx >> 3;
            int c4  = (idx & 7) << 2;
            float4 av = *(const float4*)(A + (size_t)(bm + row) * K + k0 + c4);
            split_store4(av, &Ah[row][c4], &Al[row][c4]);
            float4 bv = *(const float4*)(Bsel + (size_t)(noff + row) * K + k0 + c4);
            split_store4(bv, &Bh[row][c4], &Bl[row][c4]);
        }
        __syncthreads();

        #pragma unroll
        for (int ks = 0; ks < 32; ks += 16) {
            unsigned ah[4][4], al[4][4];
            #pragma unroll
            for (int mt = 0; mt < 4; mt++) {
                int r = wm + mt * 16;
                ah[mt][0] = *(const unsigned*)&Ah[r + g    ][ks + 2 * t];
                ah[mt][1] = *(const unsigned*)&Ah[r + g + 8][ks + 2 * t];
                ah[mt][2] = *(const unsigned*)&Ah[r + g    ][ks + 2 * t + 8];
                ah[mt][3] = *(const unsigned*)&Ah[r + g + 8][ks + 2 * t + 8];
                al[mt][0] = *(const unsigned*)&Al[r + g    ][ks + 2 * t];
                al[mt][1] = *(const unsigned*)&Al[r + g + 8][ks + 2 * t];
                al[mt][2] = *(const unsigned*)&Al[r + g    ][ks + 2 * t + 8];
                al[mt][3] = *(const unsigned*)&Al[r + g + 8][ks + 2 * t + 8];
            }
            unsigned bh[4][2], bl[4][2];
            #pragma unroll
            for (int nt = 0; nt < 4; nt++) {
                int c = wn + nt * 8;
                bh[nt][0] = *(const unsigned*)&Bh[c + g][ks + 2 * t];
                bh[nt][1] = *(const unsigned*)&Bh[c + g][ks + 2 * t + 8];
                bl[nt][0] = *(const unsigned*)&Bl[c + g][ks + 2 * t];
                bl[nt][1] = *(const unsigned*)&Bl[c + g][ks + 2 * t + 8];
            }
            #pragma unroll
            for (int mt = 0; mt < 4; mt++)
                #pragma unroll
                for (int nt = 0; nt < 4; nt++) {
                    mma_bf16(acc[mt][nt], ah[mt], bh[nt]);
                    mma_bf16(acc[mt][nt], ah[mt], bl[nt]);
                    mma_bf16(acc[mt][nt], al[mt], bh[nt]);
                }
        }
        __syncthreads();
    }

    #pragma unroll
    for (int mt = 0; mt < 4; mt++)
        #pragma unroll
        for (int nt = 0; nt < 4; nt++) {
            int r    = bm + wm + mt * 16 + g;
            int ccol = wn + nt * 8 + 2 * t;
            float b0v = 0.f, b1v = 0.f;
            if (bias) { b0v = bias[noff + ccol]; b1v = bias[noff + ccol + 1]; }
            *(float2*)(C + (size_t)r * N + bn + ccol) =
                make_float2(acc[mt][nt][0] + b0v, acc[mt][nt][1] + b1v);
            *(float2*)(C + (size_t)(r + 8) * N + bn + ccol) =
                make_float2(acc[mt][nt][2] + b0v, acc[mt][nt][3] + b1v);
        }
}

// ---------------------------------------------------------------------------
// Flash attention with bf16-split mma. Br=Bc=64, D=64, 128 threads (4 warps).
// Each warp: 16 q-rows x all 64 keys. P stays in registers (acc->A frag map).
// ---------------------------------------------------------------------------
#define QP 72
#define ATTN_SMEM (6 * 64 * QP * 2)   /* 55296 B */

__global__ __launch_bounds__(128) void attn_kernel(
    const float* __restrict__ qkv, const float* __restrict__ amask,
    float* __restrict__ out)
{
    extern __shared__ __align__(16) __nv_bfloat16 smb[];
    __nv_bfloat16* Qh = smb;
    __nv_bfloat16* Ql = Qh + 64 * QP;
    __nv_bfloat16* Kh = Ql + 64 * QP;
    __nv_bfloat16* Kl = Kh + 64 * QP;
    __nv_bfloat16* Vh = Kl + 64 * QP;   // transposed: [d][key]
    __nv_bfloat16* Vl = Vh + 64 * QP;

    const int qt0 = blockIdx.x * 64;
    const int b   = blockIdx.y >> 4;
    const int h   = blockIdx.y & 15;
    const int kvh = h >> 2;
    const int tid  = threadIdx.x;
    const int wid  = tid >> 5;
    const int lane = tid & 31;
    const int g = lane >> 2, t = lane & 3;

    const float* qbase = qkv + (size_t)(b * SEQL + qt0) * QKVN + h * HD;
    #pragma unroll
    for (int l = 0; l < 8; l++) {
        int idx = tid + l * 128;
        int row = idx >> 4;
        int c4  = (idx & 15) << 2;
        float4 v = *(const float4*)(qbase + (size_t)row * QKVN + c4);
        split_store4(v, &Qh[row * QP + c4], &Ql[row * QP + c4]);
    }

    float o[8][4];
    #pragma unroll
    for (int dt = 0; dt < 8; dt++)
        #pragma unroll
        for (int c = 0; c < 4; c++) o[dt][c] = 0.f;
    float m0 = -1e30f, m1 = -1e30f, l0 = 0.f, l1 = 0.f;
    const int rq0 = qt0 + wid * 16 + g;   // row of acc c0,c1 (c2,c3 -> rq0+8)

    const int ktmax = min(SEQL, qt0 + 63 + WIN + 1);
    for (int kt0 = 0; kt0 < ktmax; kt0 += 64) {
        const float* kbase = qkv + (size_t)(b * SEQL + kt0) * QKVN + HIDDEN + kvh * HD;
        #pragma unroll
        for (int l = 0; l < 8; l++) {
            int idx = tid + l * 128;
            int row = idx >> 4;
            int c4  = (idx & 15) << 2;
            float4 kv4 = *(const float4*)(kbase + (size_t)row * QKVN + c4);
            split_store4(kv4, &Kh[row * QP + c4], &Kl[row * QP + c4]);
            float4 vv = *(const float4*)(kbase + KVD + (size_t)row * QKVN + c4);
            float vals[4] = {vv.x, vv.y, vv.z, vv.w};
            #pragma unroll
            for (int i = 0; i < 4; i++) {
                __nv_bfloat16 hh = __float2bfloat16(vals[i]);
                __nv_bfloat16 ll = __float2bfloat16(vals[i] - __bfloat162float(hh));
                Vh[(c4 + i) * QP + row] = hh;
                Vl[(c4 + i) * QP + row] = ll;
            }
        }
        __syncthreads();

        // ---- S = Q K^T ----
        float s[8][4];
        #pragma unroll
        for (int nt = 0; nt < 8; nt++)
            #pragma unroll
            for (int c = 0; c < 4; c++) s[nt][c] = 0.f;

        #pragma unroll
        for (int ks = 0; ks < 4; ks++) {
            int d = ks * 16;
            unsigned ah[4], alr[4];
            const __nv_bfloat16* qr = &Qh[(wid * 16 + g) * QP + d + 2 * t];
            ah[0]  = *(const unsigned*)qr;
            ah[1]  = *(const unsigned*)(qr + 8 * QP);
            ah[2]  = *(const unsigned*)(qr + 8);
            ah[3]  = *(const unsigned*)(qr + 8 * QP + 8);
            const __nv_bfloat16* qrl = &Ql[(wid * 16 + g) * QP + d + 2 * t];
            alr[0] = *(const unsigned*)qrl;
            alr[1] = *(const unsigned*)(qrl + 8 * QP);
            alr[2] = *(const unsigned*)(qrl + 8);
            alr[3] = *(const unsigned*)(qrl + 8 * QP + 8);
            #pragma unroll
            for (int nt = 0; nt < 8; nt++) {
                const __nv_bfloat16* kr  = &Kh[(nt * 8 + g) * QP + d + 2 * t];
                const __nv_bfloat16* krl = &Kl[(nt * 8 + g) * QP + d + 2 * t];
                unsigned bh[2] = {*(const unsigned*)kr,  *(const unsigned*)(kr + 8)};
                unsigned bl[2] = {*(const unsigned*)krl, *(const unsigned*)(krl + 8)};
                mma_bf16(s[nt], ah, bh);
                mma_bf16(s[nt], ah, bl);
                mma_bf16(s[nt], alr, bh);
            }
        }

        // ---- scale + masks ----
        #pragma unroll
        for (int nt = 0; nt < 8; nt++) {
            int col0 = kt0 + nt * 8 + 2 * t;
            float2 amv = *(const float2*)(amask + (size_t)b * SEQL + col0);
            float a0 = amv.x * -10000.f;
            float a1 = amv.y * -10000.f;
            s[nt][0] = (col0     - rq0     > WIN) ? -1e30f : fmaf(s[nt][0], 0.125f, a0);
            s[nt][1] = (col0 + 1 - rq0     > WIN) ? -1e30f : fmaf(s[nt][1], 0.125f, a1);
            s[nt][2] = (col0     - rq0 - 8 > WIN) ? -1e30f : fmaf(s[nt][2], 0.125f, a0);
            s[nt][3] = (col0 + 1 - rq0 - 8 > WIN) ? -1e30f : fmaf(s[nt][3], 0.125f, a1);
        }

        // ---- online softmax (rows g and g+8) ----
        float mx0 = -1e30f, mx1 = -1e30f;
        #pragma unroll
        for (int nt = 0; nt < 8; nt++) {
            mx0 = fmaxf(mx0, fmaxf(s[nt][0], s[nt][1]));
            mx1 = fmaxf(mx1, fmaxf(s[nt][2], s[nt][3]));
        }
        mx0 = fmaxf(mx0, __shfl_xor_sync(0xffffffffu, mx0, 1));
        mx0 = fmaxf(mx0, __shfl_xor_sync(0xffffffffu, mx0, 2));
        mx1 = fmaxf(mx1, __shfl_xor_sync(0xffffffffu, mx1, 1));
        mx1 = fmaxf(mx1, __shfl_xor_sync(0xffffffffu, mx1, 2));
        float mn0 = fmaxf(m0, mx0), mn1 = fmaxf(m1, mx1);
        float alpha0 = __expf(m0 - mn0), alpha1 = __expf(m1 - mn1);
        m0 = mn0; m1 = mn1;
        float ls0 = 0.f, ls1 = 0.f;
        #pragma unroll
        for (int nt = 0; nt < 8; nt++) {
            s[nt][0] = __expf(s[nt][0] - mn0);
            s[nt][1] = __expf(s[nt][1] - mn0);
            s[nt][2] = __expf(s[nt][2] - mn1);
            s[nt][3] = __expf(s[nt][3] - mn1);
            ls0 += s[nt][0] + s[nt][1];
            ls1 += s[nt][2] + s[nt][3];
        }
        ls0 += __shfl_xor_sync(0xffffffffu, ls0, 1);
        ls0 += __shfl_xor_sync(0xffffffffu, ls0, 2);
        ls1 += __shfl_xor_sync(0xffffffffu, ls1, 1);
        ls1 += __shfl_xor_sync(0xffffffffu, ls1, 2);
        l0 = l0 * alpha0 + ls0;
        l1 = l1 * alpha1 + ls1;
        #pragma unroll
        for (int dt = 0; dt < 8; dt++) {
            o[dt][0] *= alpha0; o[dt][1] *= alpha0;
            o[dt][2] *= alpha1; o[dt][3] *= alpha1;
        }

        // ---- O += P V  (P from registers, split hi/lo) ----
        #pragma unroll
        for (int kp = 0; kp < 4; kp++) {
            unsigned ah[4], alr[4];
            split_pack2(s[2 * kp][0],     s[2 * kp][1],     ah[0], alr[0]);
            split_pack2(s[2 * kp][2],     s[2 * kp][3],     ah[1], alr[1]);
            split_pack2(s[2 * kp + 1][0], s[2 * kp + 1][1], ah[2], alr[2]);
            split_pack2(s[2 * kp + 1][2], s[2 * kp + 1][3], ah[3], alr[3]);
            #pragma unroll
            for (int dt = 0; dt < 8; dt++) {
                const __nv_bfloat16* vr  = &Vh[(dt * 8 + g) * QP + kp * 16 + 2 * t];
                const __nv_bfloat16* vrl = &Vl[(dt * 8 + g) * QP + kp * 16 + 2 * t];
                unsigned bh[2] = {*(const unsigned*)vr,  *(const unsigned*)(vr + 8)};
                unsigned bl[2] = {*(const unsigned*)vrl, *(const unsigned*)(vrl + 8)};
                mma_bf16(o[dt], ah, bh);
                mma_bf16(o[dt], ah, bl);
                mma_bf16(o[dt], alr, bh);
            }
        }
        __syncthreads();
    }

    float inv0 = 1.f / l0, inv1 = 1.f / l1;
    float* ob = out + (size_t)(b * SEQL + qt0 + wid * 16 + g) * HIDDEN + h * HD;
    #pragma unroll
    for (int dt = 0; dt < 8; dt++) {
        int dc = dt * 8 + 2 * t;
        *(float2*)(ob + dc) = make_float2(o[dt][0] * inv0, o[dt][1] * inv0);
        *(float2*)(ob + 8 * HIDDEN + dc) = make_float2(o[dt][2] * inv1, o[dt][3] * inv1);
    }
}

// ---------------------------------------------------------------------------
extern "C" void kernel_launch(void* const* d_in, const int* in_sizes, int n_in,
                              void* d_out, int out_size) {
    const float* hs = (const float*)d_in[0];
    const float* am = (const float*)d_in[1];
    const float* Wq = (const float*)d_in[2];
    const float* bq = (const float*)d_in[3];
    const float* Wk = (const float*)d_in[4];
    const float* bk = (const float*)d_in[5];
    const float* Wv = (const float*)d_in[6];
    const float* bv = (const float*)d_in[7];
    const float* Wo = (const float*)d_in[8];
    float* out = (float*)d_out;

    float* qkv  = nullptr;
    float* attn = nullptr;
    cudaGetSymbolAddress((void**)&qkv,  g_qkv);
    cudaGetSymbolAddress((void**)&attn, g_attn);

    sincos_kernel<<<(SEQL * 32 + 255) / 256, 256>>>();

    // fused QKV projection + bias -> g_qkv [4096 x 1536]
    hgemm_kernel<<<dim3(QKVN / 128, MTOT / 128), 256>>>(
        hs, Wq, Wk, Wv, bq, bk, bv, qkv,
        MTOT, QKVN, HIDDEN, HIDDEN, HIDDEN + KVD);

    rope_kernel<<<(MTOT * (NH + NKV) * (HD / 2) + 255) / 256, 256>>>(qkv);

    cudaFuncSetAttribute(attn_kernel, cudaFuncAttributeMaxDynamicSharedMemorySize, ATTN_SMEM);
    attn_kernel<<<dim3(SEQL / 64, BSZ * NH), 128, ATTN_SMEM>>>(qkv, am, attn);

    // output projection -> d_out
    hgemm_kernel<<<dim3(HIDDEN / 128, MTOT / 128), 256>>>(
        attn, Wo, Wo, Wo, nullptr, nullptr, nullptr, out,
        MTOT, HIDDEN, HIDDEN, 1 << 30, 1 << 30);
}

// round 3
// speedup vs baseline: 2.8188x; 1.5760x over previous
#include <cuda_runtime.h>
#include <cuda_bf16.h>
#include <math.h>

#define HIDDEN 1024
#define NH 16
#define NKV 4
#define HD 64
#define SEQL 2048
#define BSZ 2
#define KVD (NKV*HD)            /* 256  */
#define QKVN (HIDDEN + 2*KVD)   /* 1536 */
#define MTOT (BSZ*SEQL)         /* 4096 */
#define WIN 1534
#define LOG2E 1.44269504088896340736f

#define WQ_OFF 0
#define WK_OFF (1024*1024)
#define WV_OFF (1280*1024)
#define WO_OFF (1536*1024)
#define WTOT   (2560*1024)

__device__ __align__(16) float          g_qkv[(size_t)MTOT * QKVN];
__device__ __align__(16) __nv_bfloat16  g_ah[(size_t)MTOT * HIDDEN];
__device__ __align__(16) __nv_bfloat16  g_al[(size_t)MTOT * HIDDEN];
__device__ __align__(16) __nv_bfloat16  g_wh[(size_t)WTOT];
__device__ __align__(16) __nv_bfloat16  g_wl[(size_t)WTOT];
__device__ __align__(16) float          g_bias[QKVN];
__device__ __align__(16) __nv_bfloat16  g_qh[(size_t)MTOT * HIDDEN];
__device__ __align__(16) __nv_bfloat16  g_ql[(size_t)MTOT * HIDDEN];
__device__ __align__(16) __nv_bfloat16  g_kh[(size_t)MTOT * KVD];
__device__ __align__(16) __nv_bfloat16  g_kl[(size_t)MTOT * KVD];
__device__ __align__(16) __nv_bfloat16  g_vh[(size_t)MTOT * KVD];
__device__ __align__(16) __nv_bfloat16  g_vl[(size_t)MTOT * KVD];
__device__ __align__(16) __nv_bfloat16  g_oh[(size_t)MTOT * HIDDEN];
__device__ __align__(16) __nv_bfloat16  g_ol[(size_t)MTOT * HIDDEN];
__device__ __align__(16) float2         g_sc[SEQL * 32];

__device__ __forceinline__ void mma_bf16(float* c, const unsigned* a, const unsigned* b) {
    asm volatile(
        "mma.sync.aligned.m16n8k16.row.col.f32.bf16.bf16.f32 "
        "{%0,%1,%2,%3}, {%4,%5,%6,%7}, {%8,%9}, {%0,%1,%2,%3};"
        : "+f"(c[0]), "+f"(c[1]), "+f"(c[2]), "+f"(c[3])
        : "r"(a[0]), "r"(a[1]), "r"(a[2]), "r"(a[3]), "r"(b[0]), "r"(b[1]));
}
#define LDSM_X4(R, ADDR) \
    asm volatile("ldmatrix.sync.aligned.m8n8.x4.shared.b16 {%0,%1,%2,%3}, [%4];" \
        : "=r"((R)[0]), "=r"((R)[1]), "=r"((R)[2]), "=r"((R)[3]) : "r"(ADDR))
#define LDSM_X4_T(R, ADDR) \
    asm volatile("ldmatrix.sync.aligned.m8n8.x4.trans.shared.b16 {%0,%1,%2,%3}, [%4];" \
        : "=r"((R)[0]), "=r"((R)[1]), "=r"((R)[2]), "=r"((R)[3]) : "r"(ADDR))
__device__ __forceinline__ void cp16(unsigned dst, const void* src) {
    asm volatile("cp.async.cg.shared.global [%0], [%1], 16;" :: "r"(dst), "l"(src) : "memory");
}
__device__ __forceinline__ void cp_commit() { asm volatile("cp.async.commit_group;" ::: "memory"); }
template<int N> __device__ __forceinline__ void cp_wait() {
    asm volatile("cp.async.wait_group %0;" :: "n"(N) : "memory");
}
__device__ __forceinline__ float fexp2(float x) {
    float y; asm("ex2.approx.f32 %0, %1;" : "=f"(y) : "f"(x)); return y;
}
__device__ __forceinline__ void split1(float x, __nv_bfloat16& h, __nv_bfloat16& l) {
    h = __float2bfloat16(x);
    l = __float2bfloat16(x - __bfloat162float(h));
}
__device__ __forceinline__ void split_pack2(float x, float y, unsigned& hi, unsigned& lo) {
    __nv_bfloat16 hx, lx, hy, ly;
    split1(x, hx, lx); split1(y, hy, ly);
    hi = ((unsigned)__bfloat16_as_ushort(hy) << 16) | (unsigned)__bfloat16_as_ushort(hx);
    lo = ((unsigned)__bfloat16_as_ushort(ly) << 16) | (unsigned)__bfloat16_as_ushort(lx);
}

__global__ void sincos_kernel() {
    int idx = blockIdx.x * blockDim.x + threadIdx.x;
    if (idx >= SEQL * 32) return;
    int s = idx >> 5, j = idx & 31;
    double invf = exp(-(double)j * 0.28782313662425572);
    double ang  = (double)s * invf;
    g_sc[idx] = make_float2((float)sin(ang), (float)cos(ang));
}

__global__ void split_kernel(const float* __restrict__ src,
                             __nv_bfloat16* __restrict__ dh,
                             __nv_bfloat16* __restrict__ dl, int n4) {
    int i = blockIdx.x * blockDim.x + threadIdx.x;
    if (i >= n4) return;
    float4 v = ((const float4*)src)[i];
    uint2 h, l;
    split_pack2(v.x, v.y, h.x, l.x);
    split_pack2(v.z, v.w, h.y, l.y);
    ((uint2*)dh)[i] = h;
    ((uint2*)dl)[i] = l;
}

__global__ void bias_concat_kernel(const float* __restrict__ bq,
                                   const float* __restrict__ bk,
                                   const float* __restrict__ bv) {
    int i = blockIdx.x * blockDim.x + threadIdx.x;
    if (i >= QKVN) return;
    g_bias[i] = (i < HIDDEN) ? bq[i] : (i < HIDDEN + KVD ? bk[i - HIDDEN] : bv[i - HIDDEN - KVD]);
}

#define NQ_T (MTOT*NH*32)
#define NK_T (MTOT*NKV*32)
#define NV_T (MTOT*64)
__global__ void rope_split_kernel() {
    int idx = blockIdx.x * blockDim.x + threadIdx.x;
    if (idx < NQ_T) {
        int j = idx & 31, r = idx >> 5;
        int h = r % NH, m = r / NH;
        float2 sc = g_sc[((m & (SEQL - 1)) << 5) | j];
        const float* base = g_qkv + (size_t)m * QKVN + h * HD;
        float xr = base[j], xp = base[j + 32];
        float a = xr * sc.y - xp * sc.x;
        float b = xr * sc.x + xp * sc.y;
        size_t o = (size_t)m * HIDDEN + h * HD + j;
        split1(a, g_qh[o], g_ql[o]);
        split1(b, g_qh[o + 32], g_ql[o + 32]);
        return;
    }
    idx -= NQ_T;
    if (idx < NK_T) {
        int j = idx & 31, r = idx >> 5;
        int h = r % NKV, m = r / NKV;
        float2 sc = g_sc[((m & (SEQL - 1)) << 5) | j];
        const float* base = g_qkv + (size_t)m * QKVN + HIDDEN + h * HD;
        float xr = base[j], xp = base[j + 32];
        float a = xr * sc.y - xp * sc.x;
        float b = xr * sc.x + xp * sc.y;
        size_t o = (size_t)m * KVD + h * HD + j;
        split1(a, g_kh[o], g_kl[o]);
        split1(b, g_kh[o + 32], g_kl[o + 32]);
        return;
    }
    idx -= NK_T;
    if (idx < NV_T) {
        int c4 = (idx & 63) * 4, m = idx >> 6;
        float4 v = *(const float4*)(g_qkv + (size_t)m * QKVN + HIDDEN + KVD + c4);
        uint2 h, l;
        split_pack2(v.x, v.y, h.x, l.x);
        split_pack2(v.z, v.w, h.y, l.y);
        *(uint2*)(g_vh + (size_t)m * KVD + c4) = h;
        *(uint2*)(g_vl + (size_t)m * KVD + c4) = l;
    }
}

#define GP 40
#define G_STG (4*128*GP)
#define GEMM_SMEM (2*G_STG*2)

__global__ __launch_bounds__(256) void hgemm_kernel(
    const __nv_bfloat16* __restrict__ Ah, const __nv_bfloat16* __restrict__ Al,
    const __nv_bfloat16* __restrict__ Bh, const __nv_bfloat16* __restrict__ Bl,
    const float* __restrict__ bias, float* __restrict__ C, int N)
{
    extern __shared__ __align__(16) __nv_bfloat16 smg[];
    const unsigned sb = (unsigned)__cvta_generic_to_shared(smg);
    const int K = HIDDEN;
    const int bm = blockIdx.y * 128;
    const int bn = blockIdx.x * 128;
    const int tid = threadIdx.x, wid = tid >> 5, lane = tid & 31;
    const int g = lane >> 2, t = lane & 3;
    const int ln7 = lane & 7, sel = lane >> 3;
    const int wm = (wid >> 2) * 64, wn = (wid & 3) * 32;
    const int loffA = (((sel & 1) * 8 + ln7) * GP + (sel >> 1) * 8) * 2;
    const int loffB = (((sel >> 1) * 8 + ln7) * GP + (sel & 1) * 8) * 2;

    const __nv_bfloat16* srcs[4] = {Ah + (size_t)bm * K, Al + (size_t)bm * K,
                                    Bh + (size_t)bn * K, Bl + (size_t)bn * K};

    float acc[4][4][4];
    #pragma unroll
    for (int i = 0; i < 4; i++)
        #pragma unroll
        for (int j = 0; j < 4; j++)
            #pragma unroll
            for (int c = 0; c < 4; c++) acc[i][j][c] = 0.f;

    auto issue = [&](int k0, int stg) {
        #pragma unroll
        for (int l = 0; l < 8; l++) {
            int arr = l >> 1;
            int q = tid + (l & 1) * 256;
            int row = q >> 2, ch = q & 3;
            const __nv_bfloat16* s = srcs[arr] + (size_t)row * K + k0 + ch * 8;
            unsigned d = sb + (stg * G_STG + arr * 128 * GP + row * GP + ch * 8) * 2;
            cp16(d, s);
        }
    };

    issue(0, 0); cp_commit();
    const int NTK = K / 32;
    for (int kt = 0; kt < NTK; kt++) {
        if (kt + 1 < NTK) issue((kt + 1) * 32, (kt + 1) & 1);
        cp_commit();
        cp_wait<1>();
        __syncthreads();
        const unsigned base = sb + ((kt & 1) * G_STG) * 2;
        #pragma unroll
        for (int ks = 0; ks < 32; ks += 16) {
            unsigned ah[4][4], al[4][4];
            #pragma unroll
            for (int mt = 0; mt < 4; mt++) {
                LDSM_X4(ah[mt], base + ((wm + mt * 16) * GP + ks) * 2 + loffA);
                LDSM_X4(al[mt], base + (128 * GP + (wm + mt * 16) * GP + ks) * 2 + loffA);
            }
            #pragma unroll
            for (int ntp = 0; ntp < 2; ntp++) {
                unsigned bh[4], bl[4];
                LDSM_X4(bh, base + (2 * 128 * GP + (wn + ntp * 16) * GP + ks) * 2 + loffB);
                LDSM_X4(bl, base + (3 * 128 * GP + (wn + ntp * 16) * GP + ks) * 2 + loffB);
                #pragma unroll
                for (int mt = 0; mt < 4; mt++) {
                    mma_bf16(acc[mt][2 * ntp], ah[mt], &bh[0]);
                    mma_bf16(acc[mt][2 * ntp], ah[mt], &bl[0]);
                    mma_bf16(acc[mt][2 * ntp], al[mt], &bh[0]);
                    mma_bf16(acc[mt][2 * ntp + 1], ah[mt], &bh[2]);
                    mma_bf16(acc[mt][2 * ntp + 1], ah[mt], &bl[2]);
                    mma_bf16(acc[mt][2 * ntp + 1], al[mt], &bh[2]);
                }
            }
        }
        __syncthreads();
    }

    #pragma unroll
    for (int mt = 0; mt < 4; mt++)
        #pragma unroll
        for (int nt = 0; nt < 4; nt++) {
            int r = bm + wm + mt * 16 + g;
            int ccol = wn + nt * 8 + 2 * t;
            float b0v = 0.f, b1v = 0.f;
            if (bias) { b0v = bias[bn + ccol]; b1v = bias[bn + ccol + 1]; }
            *(float2*)(C + (size_t)r * N + bn + ccol) =
                make_float2(acc[mt][nt][0] + b0v, acc[mt][nt][1] + b1v);
            *(float2*)(C + (size_t)(r + 8) * N + bn + ccol) =
                make_float2(acc[mt][nt][2] + b0v, acc[mt][nt][3] + b1v);
        }
}

#define AP 72
#define A_ARR (64*AP)
#define A_STG (4*A_ARR)
#define ATTN_SMEM (2*A_STG*2)
#define SCL (0.125f * LOG2E)
#define AMS (-10000.0f * LOG2E)

__global__ __launch_bounds__(128) void attn_kernel(const float* __restrict__ amask)
{
    extern __shared__ __align__(16) __nv_bfloat16 sma[];
    const unsigned sb = (unsigned)__cvta_generic_to_shared(sma);

    const int qt0 = blockIdx.x * 64;
    const int b   = blockIdx.y >> 4;
    const int h   = blockIdx.y & 15;
    const int kvh = h >> 2;
    const int tid = threadIdx.x, wid = tid >> 5, lane = tid & 31;
    const int g = lane >> 2, t = lane & 3;
    const int ln7 = lane & 7, sel = lane >> 3;
    const int loffK = (((sel >> 1) * 8 + ln7) * AP + (sel & 1) * 8) * 2;
    const int loffV = (((sel & 1) * 8 + ln7) * AP + (sel >> 1) * 8) * 2;
    const int rq0 = qt0 + wid * 16 + g;

    unsigned Qah[4][4], Qal[4][4];
    {
        const size_t rb = (size_t)(b * SEQL + rq0) * HIDDEN + h * HD + 2 * t;
        #pragma unroll
        for (int ks = 0; ks < 4; ks++) {
            int d = ks * 16;
            Qah[ks][0] = *(const unsigned*)(g_qh + rb + d);
            Qah[ks][1] = *(const unsigned*)(g_qh + rb + 8 * HIDDEN + d);
            Qah[ks][2] = *(const unsigned*)(g_qh + rb + d + 8);
            Qah[ks][3] = *(const unsigned*)(g_qh + rb + 8 * HIDDEN + d + 8);
            Qal[ks][0] = *(const unsigned*)(g_ql + rb + d);
            Qal[ks][1] = *(const unsigned*)(g_ql + rb + 8 * HIDDEN + d);
            Qal[ks][2] = *(const unsigned*)(g_ql + rb + d + 8);
            Qal[ks][3] = *(const unsigned*)(g_ql + rb + 8 * HIDDEN + d + 8);
        }
    }

    const size_t kvbase = (size_t)(b * SEQL) * KVD + kvh * HD;
    const __nv_bfloat16* srcs[4] = {g_kh + kvbase, g_kl + kvbase,
                                    g_vh + kvbase, g_vl + kvbase};

    auto issue = [&](int kt0, int stg) {
        #pragma unroll
        for (int l = 0; l < 16; l++) {
            int arr = l >> 2;
            int q = tid + (l & 3) * 128;
            int row = q >> 3, ch = q & 7;
            const __nv_bfloat16* s = srcs[arr] + (size_t)(kt0 + row) * KVD + ch * 8;
            unsigned d = sb + (stg * A_STG + arr * A_ARR + row * AP + ch * 8) * 2;
            cp16(d, s);
        }
    };

    float o[8][4];
    #pragma unroll
    for (int dt = 0; dt < 8; dt++)
        #pragma unroll
        for (int c = 0; c < 4; c++) o[dt][c] = 0.f;
    float m0 = -1e30f, m1 = -1e30f, l0 = 0.f, l1 = 0.f;

    const int ktmax = min(SEQL, qt0 + 63 + WIN + 1);
    const int NT = (ktmax + 63) >> 6;

    issue(0, 0); cp_commit();
    for (int ti = 0; ti < NT; ti++) {
        const int kt0 = ti * 64;
        if (ti + 1 < NT) issue((ti + 1) * 64, (ti + 1) & 1);
        cp_commit();
        cp_wait<1>();
        __syncthreads();
        const unsigned base = sb + ((ti & 1) * A_STG) * 2;
        const unsigned KH = base, KL = base + A_ARR * 2;
        const unsigned VH = base + 2 * A_ARR * 2, VL = base + 3 * A_ARR * 2;

        float s[8][4];
        #pragma unroll
        for (int nt = 0; nt < 8; nt++)
            #pragma unroll
            for (int c = 0; c < 4; c++) s[nt][c] = 0.f;

        #pragma unroll
        for (int ks = 0; ks < 4; ks++) {
            #pragma unroll
            for (int ntp = 0; ntp < 4; ntp++) {
                unsigned kh[4], kl[4];
                LDSM_X4(kh, KH + (ntp * 16 * AP + ks * 16) * 2 + loffK);
                LDSM_X4(kl, KL + (ntp * 16 * AP + ks * 16) * 2 + loffK);
                mma_bf16(s[2 * ntp], Qah[ks], &kh[0]);
                mma_bf16(s[2 * ntp], Qah[ks], &kl[0]);
                mma_bf16(s[2 * ntp], Qal[ks], &kh[0]);
                mma_bf16(s[2 * ntp + 1], Qah[ks], &kh[2]);
                mma_bf16(s[2 * ntp + 1], Qah[ks], &kl[2]);
                mma_bf16(s[2 * ntp + 1], Qal[ks], &kh[2]);
            }
        }

        #pragma unroll
        for (int nt = 0; nt < 8; nt++) {
            int col0 = kt0 + nt * 8 + 2 * t;
            float2 amv = *(const float2*)(amask + (size_t)b * SEQL + col0);
            float a0 = amv.x * AMS, a1 = amv.y * AMS;
            s[nt][0] = (col0     - rq0     > WIN) ? -1e30f : fmaf(s[nt][0], SCL, a0);
            s[nt][1] = (col0 + 1 - rq0     > WIN) ? -1e30f : fmaf(s[nt][1], SCL, a1);
            s[nt][2] = (col0     - rq0 - 8 > WIN) ? -1e30f : fmaf(s[nt][2], SCL, a0);
            s[nt][3] = (col0 + 1 - rq0 - 8 > WIN) ? -1e30f : fmaf(s[nt][3], SCL, a1);
        }

        float mx0 = -1e30f, mx1 = -1e30f;
        #pragma unroll
        for (int nt = 0; nt < 8; nt++) {
            mx0 = fmaxf(mx0, fmaxf(s[nt][0], s[nt][1]));
            mx1 = fmaxf(mx1, fmaxf(s[nt][2], s[nt][3]));
        }
        mx0 = fmaxf(mx0, __shfl_xor_sync(0xffffffffu, mx0, 1));
        mx0 = fmaxf(mx0, __shfl_xor_sync(0xffffffffu, mx0, 2));
        mx1 = fmaxf(mx1, __shfl_xor_sync(0xffffffffu, mx1, 1));
        mx1 = fmaxf(mx1, __shfl_xor_sync(0xffffffffu, mx1, 2));
        float mn0 = fmaxf(m0, mx0), mn1 = fmaxf(m1, mx1);
        float alpha0 = fexp2(m0 - mn0), alpha1 = fexp2(m1 - mn1);
        m0 = mn0; m1 = mn1;
        float ls0 = 0.f, ls1 = 0.f;
        #pragma unroll
        for (int nt = 0; nt < 8; nt++) {
            s[nt][0] = fexp2(s[nt][0] - mn0);
            s[nt][1] = fexp2(s[nt][1] - mn0);
            s[nt][2] = fexp2(s[nt][2] - mn1);
            s[nt][3] = fexp2(s[nt][3] - mn1);
            ls0 += s[nt][0] + s[nt][1];
            ls1 += s[nt][2] + s[nt][3];
        }
        ls0 += __shfl_xor_sync(0xffffffffu, ls0, 1);
        ls0 += __shfl_xor_sync(0xffffffffu, ls0, 2);
        ls1 += __shfl_xor_sync(0xffffffffu, ls1, 1);
        ls1 += __shfl_xor_sync(0xffffffffu, ls1, 2);
        l0 = l0 * alpha0 + ls0;
        l1 = l1 * alpha1 + ls1;
        #pragma unroll
        for (int dt = 0; dt < 8; dt++) {
            o[dt][0] *= alpha0; o[dt][1] *= alpha0;
            o[dt][2] *= alpha1; o[dt][3] *= alpha1;
        }

        #pragma unroll
        for (int kp = 0; kp < 4; kp++) {
            unsigned pah[4], pal[4];
            split_pack2(s[2 * kp][0],     s[2 * kp][1],     pah[0], pal[0]);
            split_pack2(s[2 * kp][2],     s[2 * kp][3],     pah[1], pal[1]);
            split_pack2(s[2 * kp + 1][0], s[2 * kp + 1][1], pah[2], pal[2]);
            split_pack2(s[2 * kp + 1][2], s[2 * kp + 1][3], pah[3], pal[3]);
            #pragma unroll
            for (int dtp = 0; dtp < 4; dtp++) {
                unsigned vh[4], vl[4];
                LDSM_X4_T(vh, VH + (kp * 16 * AP + dtp * 16) * 2 + loffV);
                LDSM_X4_T(vl, VL + (kp * 16 * AP + dtp * 16) * 2 + loffV);
                mma_bf16(o[2 * dtp], pah, &vh[0]);
                mma_bf16(o[2 * dtp], pah, &vl[0]);
                mma_bf16(o[2 * dtp], pal, &vh[0]);
                mma_bf16(o[2 * dtp + 1], pah, &vh[2]);
                mma_bf16(o[2 * dtp + 1], pah, &vl[2]);
                mma_bf16(o[2 * dtp + 1], pal, &vh[2]);
            }
        }
        __syncthreads();
    }

    float inv0 = 1.f / l0, inv1 = 1.f / l1;
    const size_t ob = (size_t)(b * SEQL + rq0) * HIDDEN + h * HD + 2 * t;
    #pragma unroll
    for (int dt = 0; dt < 8; dt++) {
        int dc = dt * 8;
        unsigned hi, lo;
        split_pack2(o[dt][0] * inv0, o[dt][1] * inv0, hi, lo);
        *(unsigned*)(g_oh + ob + dc) = hi;
        *(unsigned*)(g_ol + ob + dc) = lo;
        split_pack2(o[dt][2] * inv1, o[dt][3] * inv1, hi, lo);
        *(unsigned*)(g_oh + ob + 8 * HIDDEN + dc) = hi;
        *(unsigned*)(g_ol + ob + 8 * HIDDEN + dc) = lo;
    }
}

extern "C" void kernel_launch(void* const* d_in, const int* in_sizes, int n_in,
                              void* d_out, int out_size) {
    const float* hs = (const float*)d_in[0];
    const float* am = (const float*)d_in[1];
    const float* Wq = (const float*)d_in[2];
    const float* bq = (const float*)d_in[3];
    const float* Wk = (const float*)d_in[4];
    const float* bk = (const float*)d_in[5];
    const float* Wv = (const float*)d_in[6];
    const float* bv = (const float*)d_in[7];
    const float* Wo = (const float*)d_in[8];
    float* out = (float*)d_out;

    float *qkv, *biasp;
    __nv_bfloat16 *ah, *al, *wh, *wl, *oh, *ol;
    cudaGetSymbolAddress((void**)&qkv,   g_qkv);
    cudaGetSymbolAddress((void**)&biasp, g_bias);
    cudaGetSymbolAddress((void**)&ah, g_ah);
    cudaGetSymbolAddress((void**)&al, g_al);
    cudaGetSymbolAddress((void**)&wh, g_wh);
    cudaGetSymbolAddress((void**)&wl, g_wl);
    cudaGetSymbolAddress((void**)&oh, g_oh);
    cudaGetSymbolAddress((void**)&ol, g_ol);

    cudaFuncSetAttribute(hgemm_kernel, cudaFuncAttributeMaxDynamicSharedMemorySize, GEMM_SMEM);
    cudaFuncSetAttribute(attn_kernel, cudaFuncAttributeMaxDynamicSharedMemorySize, ATTN_SMEM);

    sincos_kernel<<<(SEQL * 32 + 255) / 256, 256>>>();
    split_kernel<<<(MTOT * HIDDEN / 4 + 255) / 256, 256>>>(hs, ah, al, MTOT * HIDDEN / 4);
    split_kernel<<<(HIDDEN * HIDDEN / 4 + 255) / 256, 256>>>(Wq, wh + WQ_OFF, wl + WQ_OFF, HIDDEN * HIDDEN / 4);
    split_kernel<<<(KVD * HIDDEN / 4 + 255) / 256, 256>>>(Wk, wh + WK_OFF, wl + WK_OFF, KVD * HIDDEN / 4);
    split_kernel<<<(KVD * HIDDEN / 4 + 255) / 256, 256>>>(Wv, wh + WV_OFF, wl + WV_OFF, KVD * HIDDEN / 4);
    split_kernel<<<(HIDDEN * HIDDEN / 4 + 255) / 256, 256>>>(Wo, wh + WO_OFF, wl + WO_OFF, HIDDEN * HIDDEN / 4);
    bias_concat_kernel<<<(QKVN + 255) / 256, 256>>>(bq, bk, bv);

    hgemm_kernel<<<dim3(QKVN / 128, MTOT / 128), 256, GEMM_SMEM>>>(
        ah, al, wh, wl, biasp, qkv, QKVN);

    rope_split_kernel<<<(NQ_T + NK_T + NV_T + 255) / 256, 256>>>();

    attn_kernel<<<dim3(SEQL / 64, BSZ * NH), 128, ATTN_SMEM>>>(am);

    hgemm_kernel<<<dim3(HIDDEN / 128, MTOT / 128), 256, GEMM_SMEM>>>(
        oh, ol, wh + WO_OFF, wl + WO_OFF, nullptr, out, HIDDEN);
}